// round 2
// baseline (speedup 1.0000x reference)
#include <cuda_runtime.h>
#include <math.h>

// ---- problem constants ----
#define NBATCH 4
#define NATOMS 600
#define HALFN  300                       // NATOMS/2
#define NBINS  64
#define BIN_W      0.1171875f            // 7.5/64 (exact in fp32)
#define CUT_ADJ    7.734375f             // 7.5 + 2*BIN_W (exact)
#define GW         (7.5f / 63.0f)        // Gaussian offset spacing == width
#define GCOEFF     (-0.5f / (GW * GW))
#define QRATIO     0.36787944117144233f  // exp(2*GCOEFF*GW^2) = e^-1 (exact)
#define WIN        4                     // +-4 bins: dropped terms < exp(-10.1) ~ 4e-5 rel

#define BLOCKS_X   74
#define TOTAL_BLOCKS (BLOCKS_X * NBATCH) // 296
#define TPB        256
#define NWARPS     (TPB / 32)
#define PB_SPACE   (HALFN * NATOMS)      // 180000 balanced-triangle index space per batch

// static device scratch (no cudaMalloc allowed)
__device__ float        g_partial[TOTAL_BLOCKS * NBINS];
__device__ unsigned int g_done = 0;      // reset by the last block each run

__global__ void __launch_bounds__(TPB)
rdf_fused_kernel(const float* __restrict__ xyz, float* __restrict__ out, int out_size) {
    __shared__ float s_pos[NATOMS * 3];          // 7.2 KB: this batch's positions
    __shared__ float s_hist[NWARPS * NBINS];     // 2 KB: per-warp histograms
    __shared__ float s_cnt[NBINS];
    __shared__ float s_total;
    __shared__ int   s_last;

    const int t   = threadIdx.x;
    const int bat = blockIdx.y;
    const int wid = t >> 5;

    // stage positions + zero histograms
    const float* __restrict__ src = xyz + bat * NATOMS * 3;
    for (int k = t; k < NATOMS * 3; k += TPB) s_pos[k] = src[k];
    for (int k = t; k < NWARPS * NBINS; k += TPB) s_hist[k] = 0.0f;
    __syncthreads();

    const float cut2 = CUT_ADJ * CUT_ADJ;
    const float inv_w = 1.0f / GW;
    float* __restrict__ hist = s_hist + wid * NBINS;

    // Balanced triangle: index r in [0, 300*600). Row u (len N-1-u) pairs with
    // row N-2-u (len u+1) -> exactly N columns per u; u==N-2-u (u=299) dedup'd.
    const int stride = BLOCKS_X * TPB;
    for (int r = blockIdx.x * TPB + t; r < PB_SPACE; r += stride) {
        int u = r / NATOMS;
        int v = r - u * NATOMS;
        int i, j;
        int lim = NATOMS - 1 - u;
        if (v < lim) { i = u; j = u + 1 + v; }
        else         { i = NATOMS - 2 - u; if (i == u) continue; j = v; }

        float dx = s_pos[3 * j + 0] - s_pos[3 * i + 0];
        float dy = s_pos[3 * j + 1] - s_pos[3 * i + 1];
        float dz = s_pos[3 * j + 2] - s_pos[3 * i + 2];
        // minimum-image wrap (positions in [0,20), one wrap suffices)
        if (dx >= 10.0f) dx -= 20.0f; else if (dx < -10.0f) dx += 20.0f;
        if (dy >= 10.0f) dy -= 20.0f; else if (dy < -10.0f) dy += 20.0f;
        if (dz >= 10.0f) dz -= 20.0f; else if (dz < -10.0f) dz += 20.0f;

        float ds = dx * dx + dy * dy + dz * dz;
        if (ds >= cut2 || ds == 0.0f) continue;

        float d = sqrtf(ds);

        int kc = __float2int_rn(d * inv_w);
        int k0 = kc - WIN; if (k0 < 0) k0 = 0;
        int k1 = kc + WIN; if (k1 > NBINS - 1) k1 = NBINS - 1;

        // exp recurrence: e_{k+1} = e_k * t_k ; t_{k+1} = t_k * e^-1
        float u0 = d - (float)k0 * GW;
        float e  = __expf(GCOEFF * u0 * u0);
        float tt = __expf(GCOEFF * (GW * GW - 2.0f * u0 * GW));
        for (int k = k0; k <= k1; ++k) {
            atomicAdd(&hist[k], e);
            e *= tt;
            tt *= QRATIO;
        }
    }
    __syncthreads();

    // per-block reduction of warp histograms -> global partial slot (non-atomic,
    // every block overwrites its slot every run: no zeroing kernel needed)
    const int blin = bat * BLOCKS_X + blockIdx.x;
    if (t < NBINS) {
        float v = 0.0f;
        #pragma unroll
        for (int w = 0; w < NWARPS; ++w) v += s_hist[w * NBINS + t];
        g_partial[blin * NBINS + t] = v;
    }
    __threadfence();
    __syncthreads();
    if (t == 0) {
        unsigned int old = atomicAdd(&g_done, 1u);
        s_last = (old == TOTAL_BLOCKS - 1);
    }
    __syncthreads();
    if (!s_last) return;

    // ---- last block: finalize ----
    __threadfence();
    {
        int bin = t >> 2, part = t & 3;     // 4 threads per bin
        float v = 0.0f;
        for (int bb = part; bb < TOTAL_BLOCKS; bb += 4)
            v += g_partial[bb * NBINS + bin];
        v += __shfl_xor_sync(0xffffffffu, v, 1);
        v += __shfl_xor_sync(0xffffffffu, v, 2);
        if (part == 0) s_cnt[bin] = v;
    }
    __syncthreads();
    if (t == 0) {
        float s = 0.0f;
        for (int k = 0; k < NBINS; ++k) s += s_cnt[k];
        s_total = s;
        g_done = 0;                         // reset for next graph replay
    }
    __syncthreads();

    const float pi43 = 4.0f * 3.14159265358979f / 3.0f;
    const float num  = (2.0f * CUT_ADJ) * (2.0f * CUT_ADJ) * (2.0f * CUT_ADJ);
    if (out_size >= 2 * NBINS + 1) {
        // layout: BINS[65] then rdf[64]
        if (t <= NBINS) out[t] = (float)t * BIN_W;
        if (t < NBINS) {
            float b0 = (float)t * BIN_W;
            float b1 = (float)(t + 1) * BIN_W;
            float vol = pi43 * (b1 * b1 * b1 - b0 * b0 * b0);
            out[NBINS + 1 + t] = (s_cnt[t] / s_total) * num / (2.0f * vol);
        }
    } else {
        if (t < NBINS && t < out_size) {
            float b0 = (float)t * BIN_W;
            float b1 = (float)(t + 1) * BIN_W;
            float vol = pi43 * (b1 * b1 * b1 - b0 * b0 * b0);
            out[t] = (s_cnt[t] / s_total) * num / (2.0f * vol);
        }
    }
}

extern "C" void kernel_launch(void* const* d_in, const int* in_sizes, int n_in,
                              void* d_out, int out_size) {
    const float* xyz = (const float*)d_in[0];
    float* out = (float*)d_out;
    dim3 grid(BLOCKS_X, NBATCH);
    rdf_fused_kernel<<<grid, TPB>>>(xyz, out, out_size);
}